// round 14
// baseline (speedup 1.0000x reference)
#include <cuda_runtime.h>
#include <cstdint>

#define H    50
#define G4   200
#define E    4
#define BSZ  512
#define NTH  512
#define NCH  7       // ulonglong2 chunks per K-half
#define HPAD 56

typedef unsigned long long u64;

// named barriers: ids 1-4 = dots-done(e), 5-8 = acts-done(e), 9 = act-internal
#define BAR_SYNC_ALL(id)   asm volatile("bar.sync %0, 512;"   :: "r"(id) : "memory")
#define BAR_ARRIVE_ALL(id) asm volatile("bar.arrive %0, 512;" :: "r"(id) : "memory")
#define BAR_ACT_INT()      asm volatile("bar.sync 9, 96;" ::: "memory")

__device__ __forceinline__ void fma2(u64 &d, u64 a, u64 b) {
    asm("fma.rn.f32x2 %0, %1, %2, %0;" : "+l"(d) : "l"(a), "l"(b));
}
__device__ __forceinline__ float lo32(u64 a){ return __uint_as_float((unsigned)a); }
__device__ __forceinline__ float hi32(u64 a){ return __uint_as_float((unsigned)(a >> 32)); }
__device__ __forceinline__ float hsum2(u64 a){ return lo32(a) + hi32(a); }
__device__ __forceinline__ u64 pk2(float lo, float hi) {
    return ((u64)__float_as_uint(hi) << 32) | (u64)__float_as_uint(lo);
}
__device__ __forceinline__ float sigf(float v) {
    return __fdividef(1.0f, 1.0f + __expf(-v));
}
__device__ __forceinline__ float tanhf_(float v) {
    return 1.0f - __fdividef(2.0f, 1.0f + __expf(2.0f * v));
}

__global__ void __launch_bounds__(NTH, 1) sinelstm_kernel(
    const float* __restrict__ x,
    const float* __restrict__ W_ih1, const float* __restrict__ W_hh1,
    const float* __restrict__ b_ih1, const float* __restrict__ b_hh1,
    const float* __restrict__ W_ih2, const float* __restrict__ W_hh2,
    const float* __restrict__ b_ih2, const float* __restrict__ b_hh2,
    const float* __restrict__ W_lin, const float* __restrict__ b_lin,
    float* __restrict__ out, int T, int TP)
{
    __shared__ __align__(16) float h1s[E][HPAD];
    __shared__ __align__(16) float h2s[E][HPAD];
    // per (e,row): {g1_h0, g2_h0, g1_h1, g2_h1}; thread (row,hf) writes one float2
    __shared__ __align__(16) float4 gcomb[E][G4];
    __shared__ __align__(16) float obuf[2][E][52];
    __shared__ float outs_s[E];

    const int  t     = threadIdx.x;
    const int  base  = blockIdx.x * E;
    const bool dotw  = (t < 416);          // warps 0-12
    const bool dotth = (t < 400);
    const int  pr    = t >> 1;             // gate row
    const int  hf    = t & 1;              // K-half

    // ---- dot-side weights (row pr, half hf) ----
    u64 w1p[2 * NCH], wa[2 * NCH], wb[2 * NCH];
    float bias1 = 0.f, bias2 = 0.f;
    if (dotth) {
        #pragma unroll
        for (int p = 0; p < 2 * NCH; p++) {
            int kk = 2 * (hf * 2 * NCH + p);
            float a0 = (kk     < H) ? W_hh1[pr * H + kk]     : 0.f;
            float a1 = (kk + 1 < H) ? W_hh1[pr * H + kk + 1] : 0.f;
            w1p[p] = pk2(a0, a1);
            float c0 = (kk     < H) ? W_ih2[pr * H + kk]     : 0.f;
            float c1v= (kk + 1 < H) ? W_ih2[pr * H + kk + 1] : 0.f;
            wa[p] = pk2(c0, c1v);
            float d0 = (kk     < H) ? W_hh2[pr * H + kk]     : 0.f;
            float d1 = (kk + 1 < H) ? W_hh2[pr * H + kk + 1] : 0.f;
            wb[p] = pk2(d0, d1);
        }
        bias1 = b_ih1[pr] + b_hh1[pr];
        bias2 = b_ih2[pr] + b_hh2[pr];
    } else {
        #pragma unroll
        for (int p = 0; p < 2 * NCH; p++) { w1p[p] = 0; wa[p] = 0; wb[p] = 0; }
    }

    // ---- act-side roles: a = t-416 in [0,96) ----
    const int  a     = t - 416;
    const bool actw  = (t >= 416);
    const bool is_a1 = actw && (a < 50);
    const bool is_a2 = actw && (a >= 46);
    const int  u1    = a;                   // act1 unit
    const int  u2    = a - 46;              // act2 unit
    float wxi = 0.f, wxf = 0.f, wxg = 0.f, wxo = 0.f, wlin_u = 0.f;
    if (is_a1) {
        wxi = W_ih1[u1];          wxf = W_ih1[u1 + H];
        wxg = W_ih1[u1 + 2 * H];  wxo = W_ih1[u1 + 3 * H];
    }
    if (is_a2) wlin_u = __ldg(&W_lin[u2]);
    const float blin = b_lin[0];
    float c1s[E] = {0.f, 0.f, 0.f, 0.f};
    float c2s[E] = {0.f, 0.f, 0.f, 0.f};

    // ---- init ----
    for (int i = t; i < E * HPAD; i += NTH) { ((float*)h1s)[i] = 0.f; ((float*)h2s)[i] = 0.f; }
    for (int i = t; i < 2 * E * 52; i += NTH) ((float*)obuf)[i] = 0.f;
    __syncthreads();

    // ---- lambdas ----
    auto dots_e = [&](int e, bool wg1, bool wg2) {
        if (!dotth) return;
        const ulonglong2* h1v = (const ulonglong2*)(&h1s[e][hf * 4 * NCH]);
        const ulonglong2* h2v = (const ulonglong2*)(&h2s[e][hf * 4 * NCH]);
        u64 a1 = 0ull, a2 = 0ull, b2 = 0ull;
        if (wg1 && wg2) {
            #pragma unroll
            for (int q = 0; q < NCH; q++) {
                ulonglong2 hc = h1v[q];
                fma2(a1, w1p[2 * q], hc.x); fma2(a1, w1p[2 * q + 1], hc.y);
                fma2(a2, wa[2 * q],  hc.x); fma2(a2, wa[2 * q + 1],  hc.y);
            }
        } else if (wg1) {
            #pragma unroll
            for (int q = 0; q < NCH; q++) {
                ulonglong2 hc = h1v[q];
                fma2(a1, w1p[2 * q], hc.x); fma2(a1, w1p[2 * q + 1], hc.y);
            }
        } else {
            #pragma unroll
            for (int q = 0; q < NCH; q++) {
                ulonglong2 hc = h1v[q];
                fma2(a2, wa[2 * q],  hc.x); fma2(a2, wa[2 * q + 1],  hc.y);
            }
        }
        if (wg2) {
            #pragma unroll
            for (int q = 0; q < NCH; q++) {
                ulonglong2 hc = h2v[q];
                fma2(b2, wb[2 * q],  hc.x); fma2(b2, wb[2 * q + 1],  hc.y);
            }
        }
        float s1 = hsum2(a1);
        float s2 = hsum2(a2) + hsum2(b2);
        if (hf == 0) { s1 += bias1; s2 += bias2; }
        ((float2*)&gcomb[e][pr])[hf] = make_float2(s1, s2);
    };
    auto act1 = [&](int e, float xv) {
        float4 ri = gcomb[e][u1];
        float4 rf = gcomb[e][H + u1];
        float4 rg = gcomb[e][2 * H + u1];
        float4 ro = gcomb[e][3 * H + u1];
        float gi = ri.x + ri.z + wxi * xv;
        float gf = rf.x + rf.z + wxf * xv;
        float gg = rg.x + rg.z + wxg * xv;
        float go = ro.x + ro.z + wxo * xv;
        float c = c1s[e];
        c = sigf(gf) * c + sigf(gi) * tanhf_(gg);
        c1s[e] = c;
        h1s[e][u1] = sigf(go) * tanhf_(c);
    };
    auto act2 = [&](int e, int par) {
        float4 ri = gcomb[e][u2];
        float4 rf = gcomb[e][H + u2];
        float4 rg = gcomb[e][2 * H + u2];
        float4 ro = gcomb[e][3 * H + u2];
        float gi = ri.y + ri.w;
        float gf = rf.y + rf.w;
        float gg = rg.y + rg.w;
        float go = ro.y + ro.w;
        float c = c2s[e];
        c = sigf(gf) * c + sigf(gi) * tanhf_(gg);
        c2s[e] = c;
        float h2 = sigf(go) * tanhf_(c);
        h2s[e][u2] = h2;
        obuf[par][e][u2] = wlin_u * h2;
    };
    auto finalize = [&](int fe, int ostep, int par, bool seed) {
        const float4* ob = (const float4*)obuf[par][fe];
        float s0 = 0.f, s1 = 0.f, s2 = 0.f, s3 = 0.f;
        #pragma unroll
        for (int q = 0; q < 13; q += 4) {
            float4 v0 = ob[q];     s0 += v0.x + v0.y + v0.z + v0.w;
            if (q + 1 < 13) { float4 v1 = ob[q + 1]; s1 += v1.x + v1.y + v1.z + v1.w; }
            if (q + 2 < 13) { float4 v2 = ob[q + 2]; s2 += v2.x + v2.y + v2.z + v2.w; }
            if (q + 3 < 13) { float4 v3 = ob[q + 3]; s3 += v3.x + v3.y + v3.z + v3.w; }
        }
        float o = (s0 + s1) + (s2 + s3) + blin;
        out[(size_t)(base + fe) * TP + ostep] = o;
        if (seed) outs_s[fe] = o;
    };

    // ================= main loop: warp-specialized, per-element named barriers =================
    if (dotw) {
        for (int s = 0; s < T; s++) {
            #pragma unroll
            for (int e = 0; e < E; e++) {
                if (s > 0) BAR_SYNC_ALL(5 + e);    // wait acts(e, s-1)
                dots_e(e, true, true);              // g1(s), g2(s-1)
                BAR_ARRIVE_ALL(1 + e);
            }
        }
    } else {
        for (int s = 0; s < T; s++) {
            float xv[E];
            if (is_a1) {
                #pragma unroll
                for (int e = 0; e < E; e++)
                    xv[e] = __ldg(&x[(size_t)(base + e) * T + s]);
            }
            const int par = (s - 1) & 1;
            #pragma unroll
            for (int e = 0; e < E; e++) {
                BAR_SYNC_ALL(1 + e);               // wait dots(e, s)
                if (is_a1) act1(e, xv[e]);         // h1(s)
                if (is_a2 && s > 0) act2(e, par);  // h2(s-1), obuf
                BAR_ARRIVE_ALL(5 + e);
            }
            BAR_ACT_INT();
            if (a < E && s > 0) finalize(a, s - 1, par, false);
        }
    }
    __syncthreads();

    // ---- epilogue: g2(T-1) -> act2 -> out(T-1) + seed feedback ----
    if (dotth) {
        #pragma unroll
        for (int e = 0; e < E; e++) dots_e(e, false, true);
    }
    __syncthreads();
    if (is_a2) {
        #pragma unroll
        for (int e = 0; e < E; e++) act2(e, (T - 1) & 1);
    }
    __syncthreads();
    if (actw && a < E) finalize(a, T - 1, (T - 1) & 1, true);
    __syncthreads();

    // ================= predict loop: strict ordering =================
    for (int s = T; s < TP; s++) {
        if (dotth) {
            #pragma unroll
            for (int e = 0; e < E; e++) dots_e(e, true, false);
        }
        __syncthreads();
        if (is_a1) {
            #pragma unroll
            for (int e = 0; e < E; e++) act1(e, outs_s[e]);
        }
        __syncthreads();
        if (dotth) {
            #pragma unroll
            for (int e = 0; e < E; e++) dots_e(e, false, true);
        }
        __syncthreads();
        if (is_a2) {
            #pragma unroll
            for (int e = 0; e < E; e++) act2(e, s & 1);
        }
        __syncthreads();
        if (actw && a < E) finalize(a, s, s & 1, true);
        __syncthreads();
    }
}

extern "C" void kernel_launch(void* const* d_in, const int* in_sizes, int n_in,
                              void* d_out, int out_size) {
    const float* x     = (const float*)d_in[0];
    const float* W_ih1 = (const float*)d_in[1];
    const float* W_hh1 = (const float*)d_in[2];
    const float* b_ih1 = (const float*)d_in[3];
    const float* b_hh1 = (const float*)d_in[4];
    const float* W_ih2 = (const float*)d_in[5];
    const float* W_hh2 = (const float*)d_in[6];
    const float* b_ih2 = (const float*)d_in[7];
    const float* b_hh2 = (const float*)d_in[8];
    const float* W_lin = (const float*)d_in[9];
    const float* b_lin = (const float*)d_in[10];

    int T  = in_sizes[0] / BSZ;      // 1024
    int TP = out_size   / BSZ;       // 1056

    sinelstm_kernel<<<BSZ / E, NTH>>>(
        x, W_ih1, W_hh1, b_ih1, b_hh1,
        W_ih2, W_hh2, b_ih2, b_hh2,
        W_lin, b_lin, (float*)d_out, T, TP);
}

// round 15
// speedup vs baseline: 1.4563x; 1.4563x over previous
#include <cuda_runtime.h>
#include <cstdint>

#define H    50
#define G4   200
#define E    4
#define BSZ  512
#define NTH  448
#define NCH  7       // ulonglong2 chunks per K-half
#define HPAD 56

typedef unsigned long long u64;

__device__ __forceinline__ void fma2(u64 &d, u64 a, u64 b) {
    asm("fma.rn.f32x2 %0, %1, %2, %0;" : "+l"(d) : "l"(a), "l"(b));
}
__device__ __forceinline__ float lo32(u64 a){ return __uint_as_float((unsigned)a); }
__device__ __forceinline__ float hi32(u64 a){ return __uint_as_float((unsigned)(a >> 32)); }
__device__ __forceinline__ float hsum2(u64 a){ return lo32(a) + hi32(a); }
__device__ __forceinline__ u64 pk2(float lo, float hi) {
    return ((u64)__float_as_uint(hi) << 32) | (u64)__float_as_uint(lo);
}
__device__ __forceinline__ float sigf(float v) {
    return __fdividef(1.0f, 1.0f + __expf(-v));
}
__device__ __forceinline__ float tanhf_(float v) {
    return 1.0f - __fdividef(2.0f, 1.0f + __expf(2.0f * v));
}

__global__ void __launch_bounds__(NTH, 1) sinelstm_kernel(
    const float* __restrict__ x,
    const float* __restrict__ W_ih1, const float* __restrict__ W_hh1,
    const float* __restrict__ b_ih1, const float* __restrict__ b_hh1,
    const float* __restrict__ W_ih2, const float* __restrict__ W_hh2,
    const float* __restrict__ b_ih2, const float* __restrict__ b_hh2,
    const float* __restrict__ W_lin, const float* __restrict__ b_lin,
    float* __restrict__ out, int T, int TP)
{
    __shared__ __align__(16) float h1s[E][HPAD];
    __shared__ __align__(16) float h2s[E][HPAD];
    __shared__ u64 g1p[E][G4];                    // per (e,row): two K-half partials packed
    __shared__ u64 g2p[E][G4];
    __shared__ __align__(16) float obuf[E][52];
    __shared__ float outs_s[E];

    const int  t    = threadIdx.x;
    const int  wrp  = t >> 5;
    const int  base = blockIdx.x * E;
    const int  pr   = t >> 1;          // gate row 0..223 (>=200 masked)
    const int  hf   = t & 1;           // K-half
    const bool row_ok = (t < 400);

    // ---- register-resident weights: row pr, K-half hf ----
    u64 w1p[2 * NCH], wa[2 * NCH], wb[2 * NCH];
    float bias1 = 0.f, bias2 = 0.f, wx1 = 0.f;
    {
        #pragma unroll
        for (int p = 0; p < 2 * NCH; p++) {
            int k = 2 * (hf * 2 * NCH + p);
            float a0 = (row_ok && k     < H) ? W_hh1[pr * H + k]     : 0.f;
            float a1 = (row_ok && k + 1 < H) ? W_hh1[pr * H + k + 1] : 0.f;
            w1p[p] = pk2(a0, a1);
            float c0 = (row_ok && k     < H) ? W_ih2[pr * H + k]     : 0.f;
            float c1v= (row_ok && k + 1 < H) ? W_ih2[pr * H + k + 1] : 0.f;
            wa[p] = pk2(c0, c1v);
            float d0 = (row_ok && k     < H) ? W_hh2[pr * H + k]     : 0.f;
            float d1 = (row_ok && k + 1 < H) ? W_hh2[pr * H + k + 1] : 0.f;
            wb[p] = pk2(d0, d1);
        }
        if (row_ok) {
            bias1 = b_ih1[pr] + b_hh1[pr];
            bias2 = b_ih2[pr] + b_hh2[pr];
            wx1   = W_ih1[pr];
        }
    }

    // ---- activation tasks: t<200 -> layer1 (e,u); 200<=t<400 -> layer2 (e,u) ----
    const bool l1t = (t < 200);
    const bool l2t = (t >= 200) && (t < 400);
    const int  ui  = t % 200;
    const int  ue  = ui / 50;
    const int  uu  = ui % 50;
    float cst = 0.f;                                  // c1 (l1t) or c2 (l2t)
    const float wlin_u = l2t ? __ldg(&W_lin[uu]) : 0.f;
    const float blin   = b_lin[0];

    // ---- finalizer threads ----
    const bool fin = (t >= 440) && (t < 444);
    const int  fe  = t - 440;

    // init shared state
    for (int i = t; i < E * HPAD; i += NTH) { ((float*)h1s)[i] = 0.f; ((float*)h2s)[i] = 0.f; }
    for (int i = t; i < E * 52;   i += NTH) ((float*)obuf)[i] = 0.f;
    __syncthreads();

    // ---- helper lambdas ----
    auto dots_all = [&](int s) {   // g1(s) + g2(s-1); element order staggered per warp
        #pragma unroll
        for (int ee = 0; ee < E; ee++) {
            const int e = (ee + wrp) & 3;
            const ulonglong2* h1v = (const ulonglong2*)(&h1s[e][hf * 4 * NCH]);
            const ulonglong2* h2v = (const ulonglong2*)(&h2s[e][hf * 4 * NCH]);
            u64 a1 = 0ull, a2 = 0ull;
            #pragma unroll
            for (int q = 0; q < NCH; q++) {
                ulonglong2 hc = h1v[q];
                fma2(a1, w1p[2 * q],     hc.x);
                fma2(a1, w1p[2 * q + 1], hc.y);
                fma2(a2, wa[2 * q],      hc.x);
                fma2(a2, wa[2 * q + 1],  hc.y);
            }
            #pragma unroll
            for (int q = 0; q < NCH; q++) {
                ulonglong2 hc = h2v[q];
                fma2(a2, wb[2 * q],      hc.x);
                fma2(a2, wb[2 * q + 1],  hc.y);
            }
            float s1 = hsum2(a1);
            float s2 = hsum2(a2);
            if (hf == 0) {
                s1 += bias1 + wx1 * __ldg(&x[(size_t)(base + e) * T + s]);
                s2 += bias2;
            }
            ((float*)&g1p[e][pr])[hf] = s1;
            if (s > 0) ((float*)&g2p[e][pr])[hf] = s2;
        }
    };
    auto act1 = [&]() {
        float gi = hsum2(g1p[ue][uu]);
        float gf = hsum2(g1p[ue][H + uu]);
        float gg = hsum2(g1p[ue][2 * H + uu]);
        float go = hsum2(g1p[ue][3 * H + uu]);
        cst = sigf(gf) * cst + sigf(gi) * tanhf_(gg);
        h1s[ue][uu] = sigf(go) * tanhf_(cst);
    };
    auto act2 = [&]() {
        float gi = hsum2(g2p[ue][uu]);
        float gf = hsum2(g2p[ue][H + uu]);
        float gg = hsum2(g2p[ue][2 * H + uu]);
        float go = hsum2(g2p[ue][3 * H + uu]);
        cst = sigf(gf) * cst + sigf(gi) * tanhf_(gg);
        float h2 = sigf(go) * tanhf_(cst);
        h2s[ue][uu] = h2;
        obuf[ue][uu] = wlin_u * h2;
    };
    auto finalize_out = [&](int ostep, bool seed) {
        if (fin) {
            const float4* ob = (const float4*)obuf[fe];
            float a0 = 0.f, a1 = 0.f, a2 = 0.f, a3 = 0.f;
            #pragma unroll
            for (int q = 0; q < 13; q += 4) {
                float4 v0 = ob[q];     a0 += v0.x + v0.y + v0.z + v0.w;
                if (q + 1 < 13) { float4 v1 = ob[q + 1]; a1 += v1.x + v1.y + v1.z + v1.w; }
                if (q + 2 < 13) { float4 v2 = ob[q + 2]; a2 += v2.x + v2.y + v2.z + v2.w; }
                if (q + 3 < 13) { float4 v3 = ob[q + 3]; a3 += v3.x + v3.y + v3.z + v3.w; }
            }
            float o = (a0 + a1) + (a2 + a3) + blin;
            out[(size_t)(base + fe) * TP + ostep] = o;
            if (seed) outs_s[fe] = o;
        }
    };

    // ================= main loop: 2 barriers/step =================
    for (int s = 0; s < T; s++) {
        if (row_ok) dots_all(s);
        else if (s >= 2) finalize_out(s - 2, false);
        __syncthreads();   // A
        if (l1t) act1();
        else if (l2t && s > 0) act2();
        __syncthreads();   // B
    }

    // ---- epilogue: g2(T-1) -> act2 -> out(T-2), out(T-1), seed feedback ----
    if (row_ok) {
        #pragma unroll
        for (int ee = 0; ee < E; ee++) {
            const int e = (ee + wrp) & 3;
            const ulonglong2* h1v = (const ulonglong2*)(&h1s[e][hf * 4 * NCH]);
            const ulonglong2* h2v = (const ulonglong2*)(&h2s[e][hf * 4 * NCH]);
            u64 a2 = 0ull;
            #pragma unroll
            for (int q = 0; q < NCH; q++) {
                ulonglong2 ha = h1v[q];
                ulonglong2 hb = h2v[q];
                fma2(a2, wa[2 * q],     ha.x);
                fma2(a2, wa[2 * q + 1], ha.y);
                fma2(a2, wb[2 * q],     hb.x);
                fma2(a2, wb[2 * q + 1], hb.y);
            }
            float s2 = hsum2(a2);
            if (hf == 0) s2 += bias2;
            ((float*)&g2p[e][pr])[hf] = s2;
        }
    } else {
        finalize_out(T - 2, false);
    }
    __syncthreads();
    if (l2t) act2();
    __syncthreads();
    finalize_out(T - 1, true);
    __syncthreads();

    // ================= predict loop: strict ordering =================
    for (int s = T; s < TP; s++) {
        if (row_ok) {
            #pragma unroll
            for (int ee = 0; ee < E; ee++) {
                const int e = (ee + wrp) & 3;
                const ulonglong2* h1v = (const ulonglong2*)(&h1s[e][hf * 4 * NCH]);
                u64 a1 = 0ull;
                #pragma unroll
                for (int q = 0; q < NCH; q++) {
                    ulonglong2 hc = h1v[q];
                    fma2(a1, w1p[2 * q],     hc.x);
                    fma2(a1, w1p[2 * q + 1], hc.y);
                }
                float s1 = hsum2(a1);
                if (hf == 0) s1 += bias1 + wx1 * outs_s[e];
                ((float*)&g1p[e][pr])[hf] = s1;
            }
        }
        __syncthreads();
        if (l1t) act1();
        __syncthreads();
        if (row_ok) {
            #pragma unroll
            for (int ee = 0; ee < E; ee++) {
                const int e = (ee + wrp) & 3;
                const ulonglong2* h1v = (const ulonglong2*)(&h1s[e][hf * 4 * NCH]);
                const ulonglong2* h2v = (const ulonglong2*)(&h2s[e][hf * 4 * NCH]);
                u64 a2 = 0ull;
                #pragma unroll
                for (int q = 0; q < NCH; q++) {
                    ulonglong2 ha = h1v[q];
                    ulonglong2 hb = h2v[q];
                    fma2(a2, wa[2 * q],     ha.x);
                    fma2(a2, wa[2 * q + 1], ha.y);
                    fma2(a2, wb[2 * q],     hb.x);
                    fma2(a2, wb[2 * q + 1], hb.y);
                }
                float s2 = hsum2(a2);
                if (hf == 0) s2 += bias2;
                ((float*)&g2p[e][pr])[hf] = s2;
            }
        }
        __syncthreads();
        if (l2t) act2();
        __syncthreads();
        finalize_out(s, true);
        __syncthreads();
    }
}

extern "C" void kernel_launch(void* const* d_in, const int* in_sizes, int n_in,
                              void* d_out, int out_size) {
    const float* x     = (const float*)d_in[0];
    const float* W_ih1 = (const float*)d_in[1];
    const float* W_hh1 = (const float*)d_in[2];
    const float* b_ih1 = (const float*)d_in[3];
    const float* b_hh1 = (const float*)d_in[4];
    const float* W_ih2 = (const float*)d_in[5];
    const float* W_hh2 = (const float*)d_in[6];
    const float* b_ih2 = (const float*)d_in[7];
    const float* b_hh2 = (const float*)d_in[8];
    const float* W_lin = (const float*)d_in[9];
    const float* b_lin = (const float*)d_in[10];

    int T  = in_sizes[0] / BSZ;      // 1024
    int TP = out_size   / BSZ;       // 1056

    sinelstm_kernel<<<BSZ / E, NTH>>>(
        x, W_ih1, W_hh1, b_ih1, b_hh1,
        W_ih2, W_hh2, b_ih2, b_hh2,
        W_lin, b_lin, (float*)d_out, T, TP);
}

// round 16
// speedup vs baseline: 1.5633x; 1.0734x over previous
#include <cuda_runtime.h>
#include <cstdint>

#define H    50
#define G4   200
#define E    4
#define BSZ  512
#define NTH  448
#define NCH  7       // ulonglong2 chunks per K-half
#define HPAD 56

typedef unsigned long long u64;

__device__ __forceinline__ void fma2(u64 &d, u64 a, u64 b) {
    asm("fma.rn.f32x2 %0, %1, %2, %0;" : "+l"(d) : "l"(a), "l"(b));
}
__device__ __forceinline__ float lo32(u64 a){ return __uint_as_float((unsigned)a); }
__device__ __forceinline__ float hi32(u64 a){ return __uint_as_float((unsigned)(a >> 32)); }
__device__ __forceinline__ float hsum2(u64 a){ return lo32(a) + hi32(a); }
__device__ __forceinline__ u64 pk2(float lo, float hi) {
    return ((u64)__float_as_uint(hi) << 32) | (u64)__float_as_uint(lo);
}
__device__ __forceinline__ float sigf(float v) {
    return __fdividef(1.0f, 1.0f + __expf(-v));
}
__device__ __forceinline__ float tanhf_(float v) {
    return 1.0f - __fdividef(2.0f, 1.0f + __expf(2.0f * v));
}

__global__ void __launch_bounds__(NTH, 1) sinelstm_kernel(
    const float* __restrict__ x,
    const float* __restrict__ W_ih1, const float* __restrict__ W_hh1,
    const float* __restrict__ b_ih1, const float* __restrict__ b_hh1,
    const float* __restrict__ W_ih2, const float* __restrict__ W_hh2,
    const float* __restrict__ b_ih2, const float* __restrict__ b_hh2,
    const float* __restrict__ W_lin, const float* __restrict__ b_lin,
    float* __restrict__ out, int T, int TP)
{
    __shared__ __align__(16) float h1s[E][HPAD];
    __shared__ __align__(16) float h2s[E][HPAD];
    __shared__ u64 g1p[E][G4];                  // raw partials, halves packed
    __shared__ u64 g2p[E][G4];
    __shared__ __align__(16) float obuf[E][52];
    __shared__ float outs_s[E];
    __shared__ float xs[2][E][32];              // staged x tiles (32 steps ahead)

    const int  t    = threadIdx.x;
    const int  base = blockIdx.x * E;
    const int  pr   = t >> 1;
    const int  hf   = t & 1;
    const bool row_ok = (t < 400);

    // ---- register-resident weights: row pr, K-half hf (raw dots only) ----
    u64 w1p[2 * NCH], wa[2 * NCH], wb[2 * NCH];
    {
        #pragma unroll
        for (int p = 0; p < 2 * NCH; p++) {
            int k = 2 * (hf * 2 * NCH + p);
            float a0 = (row_ok && k     < H) ? W_hh1[pr * H + k]     : 0.f;
            float a1 = (row_ok && k + 1 < H) ? W_hh1[pr * H + k + 1] : 0.f;
            w1p[p] = pk2(a0, a1);
            float c0 = (row_ok && k     < H) ? W_ih2[pr * H + k]     : 0.f;
            float c1v= (row_ok && k + 1 < H) ? W_ih2[pr * H + k + 1] : 0.f;
            wa[p] = pk2(c0, c1v);
            float d0 = (row_ok && k     < H) ? W_hh2[pr * H + k]     : 0.f;
            float d1 = (row_ok && k + 1 < H) ? W_hh2[pr * H + k + 1] : 0.f;
            wb[p] = pk2(d0, d1);
        }
    }

    // ---- act roles: t<200 layer1 (ue,uu); 200<=t<400 layer2 ----
    const bool l1t = (t < 200);
    const bool l2t = (t >= 200) && (t < 400);
    const int  ui  = t % 200;
    const int  ue  = ui / 50;
    const int  uu  = ui % 50;
    float cst = 0.f;
    // per-gate bias (+x weights for layer1) live in act threads
    float bgi = 0.f, bgf = 0.f, bgg = 0.f, bgo = 0.f;
    float wxi = 0.f, wxf = 0.f, wxg = 0.f, wxo = 0.f;
    if (l1t) {
        bgi = b_ih1[uu] + b_hh1[uu];
        bgf = b_ih1[uu + H] + b_hh1[uu + H];
        bgg = b_ih1[uu + 2 * H] + b_hh1[uu + 2 * H];
        bgo = b_ih1[uu + 3 * H] + b_hh1[uu + 3 * H];
        wxi = W_ih1[uu];         wxf = W_ih1[uu + H];
        wxg = W_ih1[uu + 2 * H]; wxo = W_ih1[uu + 3 * H];
    }
    if (l2t) {
        bgi = b_ih2[uu] + b_hh2[uu];
        bgf = b_ih2[uu + H] + b_hh2[uu + H];
        bgg = b_ih2[uu + 2 * H] + b_hh2[uu + 2 * H];
        bgo = b_ih2[uu + 3 * H] + b_hh2[uu + 3 * H];
    }
    const float wlin_u = l2t ? __ldg(&W_lin[uu]) : 0.f;
    const float blin   = b_lin[0];

    const bool fin = (t >= 440) && (t < 444);
    const int  fe  = t - 440;
    const bool ldr = (t >= 416);                  // x-tile loader threads
    const int  li  = t - 416;                     // 0..31

    // ---- init shared state + preload x tile 0 ----
    for (int i = t; i < E * HPAD; i += NTH) { ((float*)h1s)[i] = 0.f; ((float*)h2s)[i] = 0.f; }
    for (int i = t; i < E * 52;   i += NTH) ((float*)obuf)[i] = 0.f;
    if (ldr) {
        #pragma unroll
        for (int e = 0; e < E; e++)
            xs[0][e][li] = __ldg(&x[(size_t)(base + e) * T + li]);
    }
    __syncthreads();

    // ---- lambdas ----
    auto dots_all = [&](int s) {   // raw g1(s) + g2(s-1) partials; 3 indep chains/element
        #pragma unroll
        for (int e = 0; e < E; e++) {
            const ulonglong2* h1v = (const ulonglong2*)(&h1s[e][hf * 4 * NCH]);
            const ulonglong2* h2v = (const ulonglong2*)(&h2s[e][hf * 4 * NCH]);
            u64 a1 = 0ull, a2 = 0ull, b2 = 0ull;
            #pragma unroll
            for (int q = 0; q < NCH; q++) {
                ulonglong2 hc = h1v[q];
                fma2(a1, w1p[2 * q],     hc.x);
                fma2(a1, w1p[2 * q + 1], hc.y);
                fma2(a2, wa[2 * q],      hc.x);
                fma2(a2, wa[2 * q + 1],  hc.y);
            }
            #pragma unroll
            for (int q = 0; q < NCH; q++) {
                ulonglong2 hc = h2v[q];
                fma2(b2, wb[2 * q],      hc.x);
                fma2(b2, wb[2 * q + 1],  hc.y);
            }
            ((float*)&g1p[e][pr])[hf] = hsum2(a1);
            if (s > 0) ((float*)&g2p[e][pr])[hf] = hsum2(a2) + hsum2(b2);
        }
    };
    auto act1 = [&](float xv) {
        float gi = hsum2(g1p[ue][uu])         + bgi + wxi * xv;
        float gf = hsum2(g1p[ue][H + uu])     + bgf + wxf * xv;
        float gg = hsum2(g1p[ue][2 * H + uu]) + bgg + wxg * xv;
        float go = hsum2(g1p[ue][3 * H + uu]) + bgo + wxo * xv;
        cst = sigf(gf) * cst + sigf(gi) * tanhf_(gg);
        h1s[ue][uu] = sigf(go) * tanhf_(cst);
    };
    auto act2 = [&]() {
        float gi = hsum2(g2p[ue][uu])         + bgi;
        float gf = hsum2(g2p[ue][H + uu])     + bgf;
        float gg = hsum2(g2p[ue][2 * H + uu]) + bgg;
        float go = hsum2(g2p[ue][3 * H + uu]) + bgo;
        cst = sigf(gf) * cst + sigf(gi) * tanhf_(gg);
        float h2 = sigf(go) * tanhf_(cst);
        h2s[ue][uu] = h2;
        obuf[ue][uu] = wlin_u * h2;
    };
    auto finalize_out = [&](int ostep, bool seed) {
        if (fin) {
            const float4* ob = (const float4*)obuf[fe];
            float a0 = 0.f, a1 = 0.f, a2 = 0.f, a3 = 0.f;
            #pragma unroll
            for (int q = 0; q < 13; q += 4) {
                float4 v0 = ob[q];     a0 += v0.x + v0.y + v0.z + v0.w;
                if (q + 1 < 13) { float4 v1 = ob[q + 1]; a1 += v1.x + v1.y + v1.z + v1.w; }
                if (q + 2 < 13) { float4 v2 = ob[q + 2]; a2 += v2.x + v2.y + v2.z + v2.w; }
                if (q + 3 < 13) { float4 v3 = ob[q + 3]; a3 += v3.x + v3.y + v3.z + v3.w; }
            }
            float o = (a0 + a1) + (a2 + a3) + blin;
            out[(size_t)(base + fe) * TP + ostep] = o;
            if (seed) outs_s[fe] = o;
        }
    };

    // ================= main loop: 2 barriers/step =================
    for (int s = 0; s < T; s++) {
        if (row_ok) {
            dots_all(s);
        } else {
            if (ldr && (s & 31) == 0 && s + 32 < T) {   // prefetch next x tile
                const int nb = ((s >> 5) & 1) ^ 1;
                #pragma unroll
                for (int e = 0; e < E; e++)
                    xs[nb][e][li] = __ldg(&x[(size_t)(base + e) * T + (s + 32 + li)]);
            }
            if (s >= 2) finalize_out(s - 2, false);
        }
        __syncthreads();   // A
        if (l1t) act1(xs[(s >> 5) & 1][ue][s & 31]);
        else if (l2t && s > 0) act2();
        __syncthreads();   // B
    }

    // ---- epilogue: g2(T-1) -> act2 -> out(T-2), out(T-1), seed feedback ----
    if (row_ok) {
        #pragma unroll
        for (int e = 0; e < E; e++) {
            const ulonglong2* h1v = (const ulonglong2*)(&h1s[e][hf * 4 * NCH]);
            const ulonglong2* h2v = (const ulonglong2*)(&h2s[e][hf * 4 * NCH]);
            u64 a2 = 0ull, b2 = 0ull;
            #pragma unroll
            for (int q = 0; q < NCH; q++) {
                ulonglong2 ha = h1v[q];
                ulonglong2 hb = h2v[q];
                fma2(a2, wa[2 * q],     ha.x);
                fma2(a2, wa[2 * q + 1], ha.y);
                fma2(b2, wb[2 * q],     hb.x);
                fma2(b2, wb[2 * q + 1], hb.y);
            }
            ((float*)&g2p[e][pr])[hf] = hsum2(a2) + hsum2(b2);
        }
    } else {
        finalize_out(T - 2, false);
    }
    __syncthreads();
    if (l2t) act2();
    __syncthreads();
    finalize_out(T - 1, true);
    __syncthreads();

    // ================= predict loop: strict ordering =================
    for (int s = T; s < TP; s++) {
        if (row_ok) {
            #pragma unroll
            for (int e = 0; e < E; e++) {
                const ulonglong2* h1v = (const ulonglong2*)(&h1s[e][hf * 4 * NCH]);
                u64 a1 = 0ull;
                #pragma unroll
                for (int q = 0; q < NCH; q++) {
                    ulonglong2 hc = h1v[q];
                    fma2(a1, w1p[2 * q],     hc.x);
                    fma2(a1, w1p[2 * q + 1], hc.y);
                }
                ((float*)&g1p[e][pr])[hf] = hsum2(a1);
            }
        }
        __syncthreads();
        if (l1t) act1(outs_s[ue]);
        __syncthreads();
        if (row_ok) {
            #pragma unroll
            for (int e = 0; e < E; e++) {
                const ulonglong2* h1v = (const ulonglong2*)(&h1s[e][hf * 4 * NCH]);
                const ulonglong2* h2v = (const ulonglong2*)(&h2s[e][hf * 4 * NCH]);
                u64 a2 = 0ull, b2 = 0ull;
                #pragma unroll
                for (int q = 0; q < NCH; q++) {
                    ulonglong2 ha = h1v[q];
                    ulonglong2 hb = h2v[q];
                    fma2(a2, wa[2 * q],     ha.x);
                    fma2(a2, wa[2 * q + 1], ha.y);
                    fma2(b2, wb[2 * q],     hb.x);
                    fma2(b2, wb[2 * q + 1], hb.y);
                }
                ((float*)&g2p[e][pr])[hf] = hsum2(a2) + hsum2(b2);
            }
        }
        __syncthreads();
        if (l2t) act2();
        __syncthreads();
        finalize_out(s, true);
        __syncthreads();
    }
}

extern "C" void kernel_launch(void* const* d_in, const int* in_sizes, int n_in,
                              void* d_out, int out_size) {
    const float* x     = (const float*)d_in[0];
    const float* W_ih1 = (const float*)d_in[1];
    const float* W_hh1 = (const float*)d_in[2];
    const float* b_ih1 = (const float*)d_in[3];
    const float* b_hh1 = (const float*)d_in[4];
    const float* W_ih2 = (const float*)d_in[5];
    const float* W_hh2 = (const float*)d_in[6];
    const float* b_ih2 = (const float*)d_in[7];
    const float* b_hh2 = (const float*)d_in[8];
    const float* W_lin = (const float*)d_in[9];
    const float* b_lin = (const float*)d_in[10];

    int T  = in_sizes[0] / BSZ;      // 1024
    int TP = out_size   / BSZ;       // 1056

    sinelstm_kernel<<<BSZ / E, NTH>>>(
        x, W_ih1, W_hh1, b_ih1, b_hh1,
        W_ih2, W_hh2, b_ih2, b_hh2,
        W_lin, b_lin, (float*)d_out, T, TP);
}